// round 2
// baseline (speedup 1.0000x reference)
#include <cuda_runtime.h>
#include <cuda_bf16.h>
#include <cstdint>

// ---------------- problem constants ----------------
#define B       8
#define N       4096
#define S       1024          // NPOINT
#define NS      32            // NSAMPLE
#define CIN     64
#define CMLP    128
#define COUT    256
#define BN_EPS  1e-5f
#define M_TOT   (B*S*NS)      // 262144 samples per channel for BN

// ---------------- device scratch (no allocs allowed) ----------------
__device__ float4 g_cent[B * S];                       // FPS centroids (new_xyz)
__device__ float  g_feats[(size_t)B * N * CMLP];       // points @ W1 + b1   (16 MB)
__device__ int    g_gidx[B * S * NS];                  // ball query indices (1 MB)
__device__ float  g_sum[COUT];
__device__ float  g_sumsq[COUT];

// ---------------- kernel: zero BN stats ----------------
__global__ void zero_stats_kernel() {
    g_sum[threadIdx.x] = 0.f;
    g_sumsq[threadIdx.x] = 0.f;
}

// ---------------- kernel: farthest point sampling ----------------
// One block per batch, 512 threads, 8 points per thread (registers).
// Distances computed with explicit rn ops (no fma) to bit-match XLA:
//   d = ((dx*dx) + (dy*dy)) + (dz*dz)
__global__ __launch_bounds__(512) void fps_kernel(const float* __restrict__ xyz) {
    const int b = blockIdx.x;
    const float* X = xyz + (size_t)b * N * 3;
    const int tid = threadIdx.x;
    const int lane = tid & 31, wid = tid >> 5;

    float px[8], py[8], pz[8], dmin[8];
#pragma unroll
    for (int j = 0; j < 8; j++) {
        int p = tid + j * 512;
        px[j] = X[p * 3 + 0];
        py[j] = X[p * 3 + 1];
        pz[j] = X[p * 3 + 2];
        dmin[j] = 1e10f;
    }

    __shared__ float s_wv[16];
    __shared__ int   s_wi[16];
    __shared__ int   s_far;
    __shared__ float s_c[3];
    if (tid == 0) s_far = 0;
    __syncthreads();

    for (int it = 0; it < S; it++) {
        if (tid == 0) {
            int f = s_far;
            float cx = X[f * 3 + 0], cy = X[f * 3 + 1], cz = X[f * 3 + 2];
            s_c[0] = cx; s_c[1] = cy; s_c[2] = cz;
            g_cent[b * S + it] = make_float4(cx, cy, cz, 0.f);
        }
        __syncthreads();
        const float cx = s_c[0], cy = s_c[1], cz = s_c[2];

        float bv = -1.f;  int bi = 0x7fffffff;
#pragma unroll
        for (int j = 0; j < 8; j++) {
            float dx = __fsub_rn(px[j], cx);
            float dy = __fsub_rn(py[j], cy);
            float dz = __fsub_rn(pz[j], cz);
            float d  = __fadd_rn(__fadd_rn(__fmul_rn(dx, dx), __fmul_rn(dy, dy)),
                                 __fmul_rn(dz, dz));
            float dm = fminf(dmin[j], d);
            dmin[j] = dm;
            if (dm > bv) { bv = dm; bi = tid + j * 512; }   // strict > keeps lowest index
        }
        // warp argmax reduce (tie -> lowest index, matching jnp.argmax)
#pragma unroll
        for (int o = 16; o > 0; o >>= 1) {
            float ov = __shfl_down_sync(0xffffffffu, bv, o);
            int   oi = __shfl_down_sync(0xffffffffu, bi, o);
            if (ov > bv || (ov == bv && oi < bi)) { bv = ov; bi = oi; }
        }
        if (lane == 0) { s_wv[wid] = bv; s_wi[wid] = bi; }
        __syncthreads();
        if (wid == 0) {
            float v = (lane < 16) ? s_wv[lane] : -2.f;
            int   i = (lane < 16) ? s_wi[lane] : 0x7fffffff;
#pragma unroll
            for (int o = 16; o > 0; o >>= 1) {
                float ov = __shfl_down_sync(0xffffffffu, v, o);
                int   oi = __shfl_down_sync(0xffffffffu, i, o);
                if (ov > v || (ov == v && oi < i)) { v = ov; i = oi; }
            }
            if (lane == 0) s_far = i;    // same thread (tid 0) reads it next iter
        }
    }
}

// ---------------- kernel: feats = points @ W1 + b1 ----------------
// block: 64 rows x 128 cols, K=64.  grid (64, 8), 256 threads.
__global__ __launch_bounds__(256) void feats_kernel(const float* __restrict__ points,
                                                    const float* __restrict__ W1,
                                                    const float* __restrict__ b1) {
    __shared__ float Ps[CIN * 68];        // k-major, padded: Ps[k*68 + r], r<64
    __shared__ float Ws[32 * CMLP];       // K-chunk of 32: Ws[k*128 + c]

    const int b  = blockIdx.y;
    const int r0 = blockIdx.x * 64;
    const int t  = threadIdx.x;
    const int tx = t & 15;                // 8 cols each
    const int ty = t >> 4;                // 4 rows each

    // load+transpose the points tile (64 rows x 64 k)
    for (int i = t; i < 64 * CIN; i += 256) {
        int r = i >> 6, k = i & 63;
        Ps[k * 68 + r] = points[((size_t)b * N + r0 + r) * CIN + k];
    }

    float acc[4][8];
#pragma unroll
    for (int i = 0; i < 4; i++)
#pragma unroll
        for (int j = 0; j < 8; j++) acc[i][j] = 0.f;

    for (int kk = 0; kk < CIN; kk += 32) {
        __syncthreads();
#pragma unroll
        for (int i = 0; i < 16; i++)
            Ws[(i * 2 + (t >> 7)) * CMLP + (t & 127)] =
                W1[(kk + i * 2 + (t >> 7)) * CMLP + (t & 127)];
        __syncthreads();
#pragma unroll
        for (int k = 0; k < 32; k++) {
            float a[4], w[8];
            const float* ps = Ps + (kk + k) * 68 + ty * 4;
#pragma unroll
            for (int i = 0; i < 4; i++) a[i] = ps[i];
            const float* ws = Ws + k * CMLP + tx * 8;
#pragma unroll
            for (int j = 0; j < 8; j++) w[j] = ws[j];
#pragma unroll
            for (int i = 0; i < 4; i++)
#pragma unroll
                for (int j = 0; j < 8; j++) acc[i][j] += a[i] * w[j];
        }
    }

    float bias[8];
#pragma unroll
    for (int j = 0; j < 8; j++) bias[j] = b1[tx * 8 + j];
#pragma unroll
    for (int i = 0; i < 4; i++) {
        size_t row = (size_t)b * N + r0 + ty * 4 + i;
        float* o = g_feats + row * CMLP + tx * 8;
#pragma unroll
        for (int j = 0; j < 8; j++) o[j] = acc[i][j] + bias[j];
    }
}

// ---------------- kernel: ball query ----------------
// one warp per centroid; first-32-by-index selection via ballot prefix.
__global__ __launch_bounds__(256) void ballq_kernel(const float* __restrict__ xyz) {
    const float R2 = (float)(0.15 * 0.15);   // f64 product cast to f32, matching JAX
    const int w    = blockIdx.x * 8 + (threadIdx.x >> 5);
    const int lane = threadIdx.x & 31;
    const int b    = w >> 10;
    const float* X = xyz + (size_t)b * N * 3;

    float4 c = g_cent[w];
    int count = 0;
    int first = -1;
    int* out = g_gidx + w * NS;

    for (int c0 = 0; c0 < N; c0 += 32) {
        int p = c0 + lane;
        float x = X[p * 3 + 0], y = X[p * 3 + 1], z = X[p * 3 + 2];
        float dx = __fsub_rn(x, c.x), dy = __fsub_rn(y, c.y), dz = __fsub_rn(z, c.z);
        float d = __fadd_rn(__fadd_rn(__fmul_rn(dx, dx), __fmul_rn(dy, dy)),
                            __fmul_rn(dz, dz));
        bool ok = !(d > R2);
        unsigned m = __ballot_sync(0xffffffffu, ok);
        if (count == 0 && m) first = c0 + __ffs(m) - 1;
        int pos = count + __popc(m & ((1u << lane) - 1));
        if (ok && pos < NS) out[pos] = p;
        count += __popc(m);
        if (count >= NS) break;     // warp-uniform (count derived from ballot)
    }
    // pad with the first in-ball index (count >= 1 always: centroid is a point)
    for (int i = count + lane; i < NS; i += 32) out[i] = first;
}

// ---------------- kernel: gather-GEMM + BN stats + maxpool ----------------
// one block per (b,s): h(32x256) = feats[gidx] (32x128) @ Wc + bc.
// 256 threads, one output column each (32 rows packed as 16 f32x2 accumulators).
__global__ __launch_bounds__(256) void group_gemm_kernel(const float* __restrict__ Wc,
                                                         const float* __restrict__ bc,
                                                         float* __restrict__ out) {
    __shared__ float As[CMLP * 32];    // k-major: As[k*32 + r]   (16 KB)
    __shared__ float Ws[16 * COUT];    // K-chunk of 16           (16 KB)

    const int bs = blockIdx.x;
    const int b  = bs >> 10;
    const int t  = threadIdx.x;

    // gather A: r = t%32, k-range = (t/32)*16 .. +15  (per-thread 64B contiguous)
    {
        const int r  = t & 31;
        const int kb = (t >> 5) * 16;
        const int row = g_gidx[bs * NS + r];
        const float* fr = g_feats + ((size_t)b * N + row) * CMLP + kb;
#pragma unroll
        for (int i = 0; i < 16; i++) As[(kb + i) * 32 + r] = fr[i];
    }

    unsigned long long acc[16];
#pragma unroll
    for (int j = 0; j < 16; j++) acc[j] = 0ull;

    const int c = t;
    for (int kk = 0; kk < CMLP; kk += 16) {
        __syncthreads();
#pragma unroll
        for (int i = 0; i < 16; i++)
            Ws[i * COUT + t] = Wc[(kk + i) * COUT + t];
        __syncthreads();
#pragma unroll
        for (int k = 0; k < 16; k++) {
            float wv = Ws[k * COUT + c];
            unsigned long long w2;
            asm("mov.b64 %0, {%1,%1};" : "=l"(w2) : "f"(wv));
            const float* ap = As + (kk + k) * 32;
#pragma unroll
            for (int j = 0; j < 16; j++) {
                unsigned long long a2 =
                    *reinterpret_cast<const unsigned long long*>(ap + 2 * j);
                asm("fma.rn.f32x2 %0, %1, %2, %0;" : "+l"(acc[j]) : "l"(a2), "l"(w2));
            }
        }
    }

    const float bias = bc[c];
    float maxv = -1e30f, sum = 0.f, sq = 0.f;
#pragma unroll
    for (int j = 0; j < 16; j++) {
        float lo, hi;
        asm("mov.b64 {%0,%1}, %2;" : "=f"(lo), "=f"(hi) : "l"(acc[j]));
        lo += bias; hi += bias;
        maxv = fmaxf(maxv, fmaxf(lo, hi));
        sum += lo + hi;
        sq  += lo * lo + hi * hi;
    }
    out[bs * COUT + c] = maxv;                 // raw max(h); normalized in pass 2
    atomicAdd(&g_sum[c], sum);                 // RED (no return)
    atomicAdd(&g_sumsq[c], sq);
}

// ---------------- kernel: BN normalize + relu (in place on d_out) ----------------
__global__ __launch_bounds__(256) void norm_kernel(float* __restrict__ out,
                                                   const float* __restrict__ gamma,
                                                   const float* __restrict__ beta) {
    const int c = threadIdx.x;                 // 256 channels = blockDim
    const size_t idx = (size_t)blockIdx.x * COUT + c;
    const float inv_m = 1.f / (float)M_TOT;
    float mean = g_sum[c] * inv_m;
    float var  = g_sumsq[c] * inv_m - mean * mean;
    float rstd = 1.f / sqrtf(var + BN_EPS);
    float h = out[idx];
    float v = (h - mean) * rstd * gamma[c] + beta[c];
    out[idx] = fmaxf(v, 0.f);
}

// ---------------- launch ----------------
extern "C" void kernel_launch(void* const* d_in, const int* in_sizes, int n_in,
                              void* d_out, int out_size) {
    const float* xyz    = (const float*)d_in[0];
    // d_in[1] = t  (unused by the reference)
    const float* points = (const float*)d_in[2];
    const float* W1     = (const float*)d_in[3];
    const float* b1     = (const float*)d_in[4];
    const float* Wc     = (const float*)d_in[5];
    const float* bc     = (const float*)d_in[6];
    const float* gamma  = (const float*)d_in[7];
    const float* beta   = (const float*)d_in[8];
    float* out = (float*)d_out;

    zero_stats_kernel<<<1, 256>>>();
    fps_kernel<<<B, 512>>>(xyz);
    feats_kernel<<<dim3(64, B), 256>>>(points, W1, b1);
    ballq_kernel<<<(B * S) / 8, 256>>>(xyz);
    group_gemm_kernel<<<B * S, 256>>>(Wc, bc, out);
    norm_kernel<<<(B * S * COUT) / 256, 256>>>(out, gamma, beta);
}